// round 1
// baseline (speedup 1.0000x reference)
#include <cuda_runtime.h>

#define BDIM 128
#define HDIM 32
#define SDIM 64
#define DDIM 128
#define STARTLEN 32
#define ATTN_SCALE 0.125f

#define KPAD 132            // K rows padded: conflict-free QK reads, 16B-aligned rows
#define NT 384              // 12 warps

// SMEM layout (float offsets)
#define KS_OFF 0                                  // 2 * 64 * 132 = 16896
#define VS_OFF (KS_OFF + 2 * SDIM * KPAD)         // 2 * 64 * 128 = 16384
#define XS_OFF (VS_OFF + 2 * SDIM * DDIM)         // 2 * 128
#define QS_OFF (XS_OFF + 2 * DDIM)                // 2 * 128
#define ATT_OFF (QS_OFF + 2 * DDIM)               // 2 * 64
#define AO_OFF (ATT_OFF + 2 * SDIM)               // 2 * 128
#define RED_OFF (AO_OFF + 2 * DDIM)               // 4 * 6 * 128 = 3072
#define SMEM_FLOATS (RED_OFF + 4 * 6 * DDIM)      // 37248 floats = 148992 B

__global__ void __launch_bounds__(NT, 1)
attn_decode_kernel(const float* __restrict__ x_in,
                   const float* __restrict__ k_in,
                   const float* __restrict__ v_in,
                   const float* __restrict__ wq,
                   const float* __restrict__ wk,
                   const float* __restrict__ wv,
                   const float* __restrict__ wo,
                   float* __restrict__ k_out,
                   float* __restrict__ v_out,
                   float* __restrict__ x_out)
{
    extern __shared__ float sm[];
    float* Ks  = sm + KS_OFF;   // [2][64][132] row-major, padded
    float* Vs  = sm + VS_OFF;   // [2][64][128] row-major
    float* xs  = sm + XS_OFF;   // [2][128] current token
    float* qs  = sm + QS_OFF;   // [2][128]
    float* att = sm + ATT_OFF;  // [2][64] scores -> probs
    float* ao  = sm + AO_OFF;   // [2][128] attention output
    float* red = sm + RED_OFF;  // partial-sum scratch

    const int t  = threadIdx.x;
    const int h  = blockIdx.x >> 6;          // 64 batch-pairs per head
    const int b0 = (blockIdx.x & 63) << 1;   // first batch of the pair

    // ---- load K, V caches and x into SMEM ----
    for (int b = 0; b < 2; ++b) {
        const float4* kin = (const float4*)(k_in + (size_t)((b0 + b) * HDIM + h) * (SDIM * DDIM));
        const float4* vin = (const float4*)(v_in + (size_t)((b0 + b) * HDIM + h) * (SDIM * DDIM));
        float* kb = Ks + b * (SDIM * KPAD);
        float* vb = Vs + b * (SDIM * DDIM);
        for (int idx = t; idx < SDIM * DDIM / 4; idx += NT) {
            int s = idx >> 5, j = idx & 31;               // 32 float4 per row
            float4 kv = kin[idx];
            *(float4*)(kb + s * KPAD + 4 * j) = kv;       // KPAD*4B = 528, 16B aligned
            float4 vv = vin[idx];
            *(float4*)(vb + (idx << 2)) = vv;
        }
        const float* xin = x_in + (size_t)((b0 + b) * HDIM + h) * DDIM;
        for (int d = t; d < DDIM; d += NT) xs[b * DDIM + d] = xin[d];
    }
    __syncthreads();

    const float4* Wq4 = (const float4*)(wq + (size_t)h * DDIM * DDIM);
    const float4* Wk4 = (const float4*)(wk + (size_t)h * DDIM * DDIM);
    const float4* Wv4 = (const float4*)(wv + (size_t)h * DDIM * DDIM);
    const float4* Wo4 = (const float4*)(wo + (size_t)h * DDIM * DDIM);

    // thread decomposition for qkv projection: 3 warpgroups = 3 matrices
    const int m    = t >> 7;        // 0=q, 1=k, 2=v (uniform per warp)
    const int r    = t & 127;
    const int c4   = r & 31;        // float4 column -> e = 4*c4 .. 4*c4+3
    const int sub  = r >> 5;        // d-range split 0..3 (32 rows each)
    const float4* Wm = (m == 0) ? Wq4 : ((m == 1) ? Wk4 : Wv4);
    const int osub = t >> 5;        // o-proj d-range split 0..11 (0..7 active)

    for (int gen = STARTLEN; gen < SDIM; ++gen) {
        // ================= QKV projections =================
        {
            float a00 = 0.f, a01 = 0.f, a02 = 0.f, a03 = 0.f;
            float a10 = 0.f, a11 = 0.f, a12 = 0.f, a13 = 0.f;
            const int d0 = sub << 5;
            #pragma unroll 8
            for (int dd = 0; dd < 32; ++dd) {
                int d = d0 + dd;
                float4 w = Wm[d * 32 + c4];               // coalesced 512B/warp, L2-fed
                float x0v = xs[d];
                float x1v = xs[DDIM + d];
                a00 += x0v * w.x; a01 += x0v * w.y; a02 += x0v * w.z; a03 += x0v * w.w;
                a10 += x1v * w.x; a11 += x1v * w.y; a12 += x1v * w.z; a13 += x1v * w.w;
            }
            float* p0 = red + (sub * 6 + m * 2 + 0) * DDIM + (c4 << 2);
            float* p1 = red + (sub * 6 + m * 2 + 1) * DDIM + (c4 << 2);
            *(float4*)p0 = make_float4(a00, a01, a02, a03);
            *(float4*)p1 = make_float4(a10, a11, a12, a13);
        }
        __syncthreads();
        // reduce 4 partials -> q / K[gen] / V[gen]
        for (int o = t; o < 6 * DDIM; o += NT) {
            int mb = o >> 7;          // 0..5 = (matrix,batch)
            int e  = o & 127;
            float v = red[(0 * 6 + mb) * DDIM + e] + red[(1 * 6 + mb) * DDIM + e]
                    + red[(2 * 6 + mb) * DDIM + e] + red[(3 * 6 + mb) * DDIM + e];
            int mm = mb >> 1, bb = mb & 1;
            if (mm == 0)       qs[bb * DDIM + e] = v;
            else if (mm == 1)  Ks[bb * (SDIM * KPAD) + gen * KPAD + e] = v;
            else               Vs[bb * (SDIM * DDIM) + gen * DDIM + e] = v;
        }
        __syncthreads();

        // ================= QK scores =================
        if (t < 256) {
            int bb = t >> 7;
            int rr = t & 127;
            int s  = rr >> 1, g2 = rr & 1;                // 2 threads per score
            const float* kr = Ks + bb * (SDIM * KPAD) + s * KPAD;
            const float* qb = qs + bb * DDIM;
            float sum = 0.f;
            #pragma unroll 8
            for (int i = 0; i < 64; ++i) {
                int d = g2 + 2 * i;
                sum += kr[d] * qb[d];
            }
            sum += __shfl_xor_sync(0xFFFFFFFFu, sum, 1);
            if (g2 == 0) att[bb * SDIM + s] = sum * ATTN_SCALE;
        }
        __syncthreads();

        // ================= softmax (warp 0 -> batch 0, warp 1 -> batch 1) =================
        if (t < 64) {
            int bb = t >> 5, l = t & 31;
            float s0 = att[bb * SDIM + l];
            float s1 = att[bb * SDIM + l + 32];
            float mx = fmaxf(s0, s1);
            #pragma unroll
            for (int o = 16; o > 0; o >>= 1) mx = fmaxf(mx, __shfl_xor_sync(0xFFFFFFFFu, mx, o));
            float e0 = __expf(s0 - mx);
            float e1 = __expf(s1 - mx);
            float sum = e0 + e1;
            #pragma unroll
            for (int o = 16; o > 0; o >>= 1) sum += __shfl_xor_sync(0xFFFFFFFFu, sum, o);
            float inv = 1.0f / sum;
            att[bb * SDIM + l]      = e0 * inv;
            att[bb * SDIM + l + 32] = e1 * inv;
        }
        __syncthreads();

        // ================= AV =================
        if (t < 256) {
            int bb = t >> 7, d = t & 127;
            const float* vb = Vs + bb * (SDIM * DDIM);
            const float* ab = att + bb * SDIM;
            float acc = 0.f;
            #pragma unroll 8
            for (int s = 0; s < SDIM; ++s) acc += ab[s] * vb[s * DDIM + d];
            ao[bb * DDIM + d] = acc;
        }
        __syncthreads();

        // ================= O projection =================
        if (osub < 8) {
            float a00 = 0.f, a01 = 0.f, a02 = 0.f, a03 = 0.f;
            float a10 = 0.f, a11 = 0.f, a12 = 0.f, a13 = 0.f;
            const int d0 = osub << 4;
            #pragma unroll 8
            for (int dd = 0; dd < 16; ++dd) {
                int d = d0 + dd;
                float4 w = Wo4[d * 32 + c4];
                float x0v = ao[d];
                float x1v = ao[DDIM + d];
                a00 += x0v * w.x; a01 += x0v * w.y; a02 += x0v * w.z; a03 += x0v * w.w;
                a10 += x1v * w.x; a11 += x1v * w.y; a12 += x1v * w.z; a13 += x1v * w.w;
            }
            float* p0 = red + (osub * 2 + 0) * DDIM + (c4 << 2);
            float* p1 = red + (osub * 2 + 1) * DDIM + (c4 << 2);
            *(float4*)p0 = make_float4(a00, a01, a02, a03);
            *(float4*)p1 = make_float4(a10, a11, a12, a13);
        }
        __syncthreads();
        if (t < 256) {
            int bb = t >> 7, e = t & 127;
            float v = 0.f;
            #pragma unroll
            for (int ss = 0; ss < 8; ++ss) v += red[(ss * 2 + bb) * DDIM + e];
            xs[bb * DDIM + e] = v;    // next step's token
        }
        __syncthreads();
    }

    // ---- epilogue: write k, v, x outputs ----
    for (int b = 0; b < 2; ++b) {
        float4* kout = (float4*)(k_out + (size_t)((b0 + b) * HDIM + h) * (SDIM * DDIM));
        float4* vout = (float4*)(v_out + (size_t)((b0 + b) * HDIM + h) * (SDIM * DDIM));
        const float* kb = Ks + b * (SDIM * KPAD);
        const float* vb = Vs + b * (SDIM * DDIM);
        for (int idx = t; idx < SDIM * DDIM / 4; idx += NT) {
            int s = idx >> 5, j = idx & 31;
            kout[idx] = *(const float4*)(kb + s * KPAD + 4 * j);
            vout[idx] = *(const float4*)(vb + (idx << 2));
        }
        float* xo = x_out + (size_t)((b0 + b) * HDIM + h) * DDIM;
        for (int d = t; d < DDIM; d += NT) xo[d] = xs[b * DDIM + d];
    }
}

extern "C" void kernel_launch(void* const* d_in, const int* in_sizes, int n_in,
                              void* d_out, int out_size)
{
    const float* x  = (const float*)d_in[0];
    const float* k  = (const float*)d_in[1];
    const float* v  = (const float*)d_in[2];
    const float* wq = (const float*)d_in[3];
    const float* wk = (const float*)d_in[4];
    const float* wv = (const float*)d_in[5];
    const float* wo = (const float*)d_in[6];

    float* out   = (float*)d_out;
    float* k_out = out;                                        // [B,H,S,D]
    float* v_out = out + (size_t)BDIM * HDIM * SDIM * DDIM;    // [B,H,S,D]
    float* x_out = out + (size_t)2 * BDIM * HDIM * SDIM * DDIM;// [B,H,1,D]

    size_t smem = SMEM_FLOATS * sizeof(float);
    cudaFuncSetAttribute(attn_decode_kernel,
                         cudaFuncAttributeMaxDynamicSharedMemorySize, (int)smem);

    attn_decode_kernel<<<BDIM * HDIM / 2, NT, smem>>>(
        x, k, v, wq, wk, wv, wo, k_out, v_out, x_out);
}

// round 2
// speedup vs baseline: 1.1700x; 1.1700x over previous
#include <cuda_runtime.h>

#define BDIM 128
#define HDIM 32
#define SDIM 64
#define DDIM 128
#define STARTLEN 32
#define ATTN_SCALE 0.125f
#define NT 256              // 8 warps

// SMEM (floats):
//  Ks  [2][64][128] = 16384
//  xs  [2][128]     = 256
//  qs  [2][128]     = 256
//  att [2][64]      = 128
//  ao  [2][128]     = 256
//  red [12][128]    = 1536   (proj partials; reused by O-proj)
#define KS_OFF   0
#define XS_OFF   (KS_OFF + 2 * SDIM * DDIM)
#define QS_OFF   (XS_OFF + 2 * DDIM)
#define ATT_OFF  (QS_OFF + 2 * DDIM)
#define AO_OFF   (ATT_OFF + 2 * SDIM)
#define RED_OFF  (AO_OFF + 2 * DDIM)
#define SMEM_FLOATS (RED_OFF + 12 * DDIM)   // 18816 floats = 75264 B -> 3 CTAs/SM

__global__ void __launch_bounds__(NT, 3)
attn_decode_kernel(const float* __restrict__ x_in,
                   const float* __restrict__ k_in,
                   const float* __restrict__ v_in,
                   const float* __restrict__ wq,
                   const float* __restrict__ wk,
                   const float* __restrict__ wv,
                   const float* __restrict__ wo,
                   float* __restrict__ k_out,
                   float*              v_out,   // read+write: keep coherent LDG
                   float* __restrict__ x_out)
{
    extern __shared__ float sm[];
    float* Ks  = sm + KS_OFF;
    float* xs  = sm + XS_OFF;
    float* qs  = sm + QS_OFF;
    float* att = sm + ATT_OFF;
    float* ao  = sm + AO_OFF;
    float* red = sm + RED_OFF;

    const int t  = threadIdx.x;
    const int w  = t >> 5;
    const int l  = t & 31;
    const int h  = blockIdx.x >> 6;
    const int b0 = (blockIdx.x & 63) << 1;

    // per-batch global V cache base (write-through cache lives in v_out)
    float* v0 = v_out + (size_t)((b0 + 0) * HDIM + h) * (SDIM * DDIM);
    float* v1 = v_out + (size_t)((b0 + 1) * HDIM + h) * (SDIM * DDIM);

    // ---- prologue: K -> smem, v_in -> v_out (full copy), x -> smem ----
    for (int b = 0; b < 2; ++b) {
        const float4* kin = (const float4*)(k_in + (size_t)((b0 + b) * HDIM + h) * (SDIM * DDIM));
        const float4* vin = (const float4*)(v_in + (size_t)((b0 + b) * HDIM + h) * (SDIM * DDIM));
        float4* vdst = (float4*)(b ? v1 : v0);
        float4* kb   = (float4*)(Ks + b * (SDIM * DDIM));
        for (int idx = t; idx < SDIM * DDIM / 4; idx += NT) {
            kb[idx]   = kin[idx];
            vdst[idx] = vin[idx];
        }
        const float* xin = x_in + (size_t)((b0 + b) * HDIM + h) * DDIM;
        for (int d = t; d < DDIM; d += NT) xs[b * DDIM + d] = xin[d];
    }
    __syncthreads();

    const float4* Wq4 = (const float4*)(wq + (size_t)h * DDIM * DDIM);
    const float4* Wk4 = (const float4*)(wk + (size_t)h * DDIM * DDIM);
    const float4* Wv4 = (const float4*)(wv + (size_t)h * DDIM * DDIM);
    const float4* Wo4 = (const float4*)(wo + (size_t)h * DDIM * DDIM);

    // proj task for warps 0..5: matrix m = w>>1, d-half dh = w&1
    const int pm  = w >> 1;
    const int pdh = w & 1;
    const float4* Wp = (pm == 0) ? Wq4 : ((pm == 1) ? Wk4 : Wv4);

    for (int gen = STARTLEN; gen < SDIM; ++gen) {
        // ============ P1: QKV projections (warps 0-5, float4 over e, d-halves) ============
        if (w < 6) {
            float4 a0 = make_float4(0.f, 0.f, 0.f, 0.f);
            float4 a1 = make_float4(0.f, 0.f, 0.f, 0.f);
            const int d0 = pdh << 6;
            #pragma unroll 8
            for (int dd = 0; dd < 64; ++dd) {
                int d = d0 + dd;
                float4 wv4 = Wp[d * 32 + l];        // 512B/warp coalesced, L2-fed
                float x0v = xs[d];
                float x1v = xs[DDIM + d];
                a0.x += x0v * wv4.x; a0.y += x0v * wv4.y; a0.z += x0v * wv4.z; a0.w += x0v * wv4.w;
                a1.x += x1v * wv4.x; a1.y += x1v * wv4.y; a1.z += x1v * wv4.z; a1.w += x1v * wv4.w;
            }
            *(float4*)(red + ((w << 1) + 0) * DDIM + (l << 2)) = a0;
            *(float4*)(red + ((w << 1) + 1) * DDIM + (l << 2)) = a1;
        }
        __syncthreads();

        // reduce 2 d-half partials -> q (smem), K[gen] (smem), V[gen] (global write-through)
        {
            const int bb = t >> 7, e = t & 127;
            #pragma unroll
            for (int m = 0; m < 3; ++m) {
                float v = red[(((m << 1) + 0) * 2 + bb) * DDIM + e]
                        + red[(((m << 1) + 1) * 2 + bb) * DDIM + e];
                if (m == 0)      qs[bb * DDIM + e] = v;
                else if (m == 1) Ks[(bb * SDIM + gen) * DDIM + e] = v;
                else             (bb ? v1 : v0)[gen * DDIM + e] = v;
            }
        }
        __syncthreads();

        // ============ P2: QK scores (warp-per-16-rows, lanes over d via float4) ============
        {
            const int bb = w >> 2;
            const int s0 = (w & 3) << 4;
            float4 q4 = *(const float4*)(qs + bb * DDIM + (l << 2));
            #pragma unroll 4
            for (int r = 0; r < 16; ++r) {
                int s = s0 + r;
                float4 k4 = *(const float4*)(Ks + (bb * SDIM + s) * DDIM + (l << 2));
                float p = k4.x * q4.x + k4.y * q4.y + k4.z * q4.z + k4.w * q4.w;
                #pragma unroll
                for (int o = 16; o > 0; o >>= 1) p += __shfl_xor_sync(0xFFFFFFFFu, p, o);
                if (l == 0) att[bb * SDIM + s] = p * ATTN_SCALE;
            }
        }
        __syncthreads();

        // ============ P3: softmax (warp 0 -> b0, warp 1 -> b1) ============
        if (t < 64) {
            int bb = t >> 5, ll = t & 31;
            float s0v = att[bb * SDIM + ll];
            float s1v = att[bb * SDIM + ll + 32];
            float mx = fmaxf(s0v, s1v);
            #pragma unroll
            for (int o = 16; o > 0; o >>= 1) mx = fmaxf(mx, __shfl_xor_sync(0xFFFFFFFFu, mx, o));
            float e0 = __expf(s0v - mx);
            float e1 = __expf(s1v - mx);
            float sum = e0 + e1;
            #pragma unroll
            for (int o = 16; o > 0; o >>= 1) sum += __shfl_xor_sync(0xFFFFFFFFu, sum, o);
            float inv = 1.0f / sum;
            att[bb * SDIM + ll]      = e0 * inv;
            att[bb * SDIM + ll + 32] = e1 * inv;
        }
        __syncthreads();

        // ============ P4: AV (V streamed from global/L2) ============
        {
            const int bb = t >> 7, d = t & 127;
            const float* vb = (bb ? v1 : v0) + d;
            const float* ab = att + bb * SDIM;
            float acc = 0.f;
            #pragma unroll 8
            for (int s = 0; s < SDIM; ++s) acc += ab[s] * vb[s * DDIM];
            ao[bb * DDIM + d] = acc;
        }
        __syncthreads();

        // ============ P5: O projection (8 warps: d-quarter x batch) ============
        {
            const int dq = w & 3, bb = w >> 2;
            float4 a = make_float4(0.f, 0.f, 0.f, 0.f);
            const int d0 = dq << 5;
            const float* aob = ao + bb * DDIM;
            #pragma unroll 8
            for (int dd = 0; dd < 32; ++dd) {
                int d = d0 + dd;
                float4 wv4 = Wo4[d * 32 + l];
                float xv = aob[d];
                a.x += xv * wv4.x; a.y += xv * wv4.y; a.z += xv * wv4.z; a.w += xv * wv4.w;
            }
            *(float4*)(red + ((dq << 1) + bb) * DDIM + (l << 2)) = a;
        }
        __syncthreads();
        {
            const int bb = t >> 7, e = t & 127;
            float v = red[(0 * 2 + bb) * DDIM + e] + red[(1 * 2 + bb) * DDIM + e]
                    + red[(2 * 2 + bb) * DDIM + e] + red[(3 * 2 + bb) * DDIM + e];
            xs[bb * DDIM + e] = v;
        }
        __syncthreads();
    }

    // ---- epilogue: write k (from smem) and x; v_out already final ----
    for (int b = 0; b < 2; ++b) {
        float4* kout = (float4*)(k_out + (size_t)((b0 + b) * HDIM + h) * (SDIM * DDIM));
        const float4* kb = (const float4*)(Ks + b * (SDIM * DDIM));
        for (int idx = t; idx < SDIM * DDIM / 4; idx += NT)
            kout[idx] = kb[idx];
        float* xo = x_out + (size_t)((b0 + b) * HDIM + h) * DDIM;
        for (int d = t; d < DDIM; d += NT) xo[d] = xs[b * DDIM + d];
    }
}

extern "C" void kernel_launch(void* const* d_in, const int* in_sizes, int n_in,
                              void* d_out, int out_size)
{
    const float* x  = (const float*)d_in[0];
    const float* k  = (const float*)d_in[1];
    const float* v  = (const float*)d_in[2];
    const float* wq = (const float*)d_in[3];
    const float* wk = (const float*)d_in[4];
    const float* wv = (const float*)d_in[5];
    const float* wo = (const float*)d_in[6];

    float* out   = (float*)d_out;
    float* k_out = out;
    float* v_out = out + (size_t)BDIM * HDIM * SDIM * DDIM;
    float* x_out = out + (size_t)2 * BDIM * HDIM * SDIM * DDIM;

    size_t smem = SMEM_FLOATS * sizeof(float);
    cudaFuncSetAttribute(attn_decode_kernel,
                         cudaFuncAttributeMaxDynamicSharedMemorySize, (int)smem);

    attn_decode_kernel<<<BDIM * HDIM / 2, NT, smem>>>(
        x, k, v, wq, wk, wv, wo, k_out, v_out, x_out);
}